// round 2
// baseline (speedup 1.0000x reference)
#include <cuda_runtime.h>
#include <cuda_bf16.h>

// Problem constants (fixed shapes from reference)
#define NTOK   4096      // B*T
#define DDIM   1024
#define HDIM   4096
#define NEXP   8
#define TOPK   2
#define NSLOTS (NTOK*TOPK)          // 8192 real slots
#define MAXSLOTS 8704               // 8192 + 8*64 padding headroom
#define MTILES (MAXSLOTS/64)        // 136

// ---------------- device scratch (static allocation only) ----------------
__device__ float g_probs[NTOK*NEXP];
__device__ int   g_eidx[NSLOTS];
__device__ float g_rw[NSLOTS];
__device__ int   g_counts[NEXP];
__device__ int   g_fill[NEXP];
__device__ int   g_offpad[NEXP+1];
__device__ int   g_list[MAXSLOTS];      // slot -> token
__device__ float g_ws[MAXSLOTS];        // slot -> routing weight (0 for pad)
__device__ int   g_sexp[MAXSLOTS];      // slot -> expert
__device__ int   g_tokslot[NSLOTS];     // (token,k) -> slot
__device__ float g_h[(size_t)MAXSLOTS*HDIM];      // ~142.6 MB
__device__ float g_outslot[(size_t)MAXSLOTS*DDIM];// ~35.7 MB

// ---------------- init (graph replays must be self-resetting) ----------------
__global__ void init_kernel() {
    int i = blockIdx.x*blockDim.x + threadIdx.x;
    if (i < NEXP) { g_counts[i] = 0; g_fill[i] = 0; }
    if (i < MAXSLOTS) { g_list[i] = 0; g_ws[i] = 0.0f; g_sexp[i] = 0; }
}

// ---------------- gating: logits, softmax, top-2, counts ----------------
__global__ void gate_kernel(const float* __restrict__ x, const float* __restrict__ Wg) {
    int n = blockIdx.x;
    int tid = threadIdx.x;
    int w = tid >> 5, lane = tid & 31;     // 8 warps, one expert per warp
    const float4* xr = (const float4*)(x + (size_t)n * DDIM);
    const float4* gr = (const float4*)(Wg + (size_t)w * DDIM);
    float s = 0.0f;
    #pragma unroll 4
    for (int i = lane; i < DDIM/4; i += 32) {
        float4 a = xr[i], b = gr[i];
        s += a.x*b.x + a.y*b.y + a.z*b.z + a.w*b.w;
    }
    #pragma unroll
    for (int o = 16; o; o >>= 1) s += __shfl_xor_sync(0xFFFFFFFFu, s, o);
    __shared__ float logits[NEXP];
    if (lane == 0) logits[w] = s;
    __syncthreads();
    if (tid == 0) {
        float m = logits[0];
        #pragma unroll
        for (int e = 1; e < NEXP; e++) m = fmaxf(m, logits[e]);
        float p[NEXP]; float sum = 0.0f;
        #pragma unroll
        for (int e = 0; e < NEXP; e++) { p[e] = expf(logits[e] - m); sum += p[e]; }
        float inv = 1.0f / sum;
        #pragma unroll
        for (int e = 0; e < NEXP; e++) { p[e] *= inv; g_probs[n*NEXP + e] = p[e]; }
        int i1 = 0;
        #pragma unroll
        for (int e = 1; e < NEXP; e++) if (p[e] > p[i1]) i1 = e;
        int i2 = -1;
        #pragma unroll
        for (int e = 0; e < NEXP; e++) {
            if (e == i1) continue;
            if (i2 < 0 || p[e] > p[i2]) i2 = e;
        }
        float r = 1.0f / (p[i1] + p[i2]);
        g_eidx[n*2]   = i1;  g_eidx[n*2+1] = i2;
        g_rw[n*2]     = p[i1]*r;  g_rw[n*2+1] = p[i2]*r;
        atomicAdd(&g_counts[i1], 1);
        atomicAdd(&g_counts[i2], 1);
    }
}

// ---------------- per-expert 64-aligned segment offsets ----------------
__global__ void offsets_kernel() {
    if (threadIdx.x == 0) {
        int off = 0;
        for (int e = 0; e < NEXP; e++) {
            g_offpad[e] = off;
            off += ((g_counts[e] + 63) >> 6) << 6;
        }
        g_offpad[NEXP] = off;
    }
}

// ---------------- scatter tokens into expert segments ----------------
__global__ void scatter_kernel() {
    int i = blockIdx.x*blockDim.x + threadIdx.x;   // (token,k) pair index
    if (i >= NSLOTS) return;
    int e = g_eidx[i];
    int pos = atomicAdd(&g_fill[e], 1);
    int slot = g_offpad[e] + pos;
    g_list[slot] = i >> 1;
    g_ws[slot] = g_rw[i];
    g_sexp[slot] = e;
    g_tokslot[i] = slot;
}

// ---------------- FC GEMM: h[slot, H] = relu(x[tok] @ Wfc[e]^T)^2 * w ----------------
// 64x64 tile, K-step 16, 256 threads, 4x4 microtile, float4 gmem loads
__global__ void fc_kernel(const float* __restrict__ x, const float* __restrict__ Wfc) {
    const int slot0 = blockIdx.x * 64;
    const int hbase = blockIdx.y * 64;
    __shared__ float As[16][65];
    __shared__ float Bs[16][65];
    __shared__ int   rowtok[64];
    __shared__ float roww[64];
    int tid = threadIdx.x;
    if (tid < 64) { rowtok[tid] = g_list[slot0 + tid]; roww[tid] = g_ws[slot0 + tid]; }
    __syncthreads();
    int e = g_sexp[slot0];
    const float* Bp = Wfc + ((size_t)e*HDIM + hbase) * DDIM;
    int tx = tid & 15, ty = tid >> 4;
    // loader mapping: 64 rows x 16 K = 256 float4
    int lr = tid >> 2;          // row 0..63
    int lk = (tid & 3) * 4;     // k offset 0,4,8,12
    float acc[4][4];
    #pragma unroll
    for (int i = 0; i < 4; i++)
        #pragma unroll
        for (int j = 0; j < 4; j++) acc[i][j] = 0.0f;

    for (int k0 = 0; k0 < DDIM; k0 += 16) {
        float4 av = *(const float4*)(x + (size_t)rowtok[lr]*DDIM + k0 + lk);
        float4 bv = *(const float4*)(Bp + (size_t)lr*DDIM + k0 + lk);
        As[lk+0][lr] = av.x; As[lk+1][lr] = av.y; As[lk+2][lr] = av.z; As[lk+3][lr] = av.w;
        Bs[lk+0][lr] = bv.x; Bs[lk+1][lr] = bv.y; Bs[lk+2][lr] = bv.z; Bs[lk+3][lr] = bv.w;
        __syncthreads();
        #pragma unroll
        for (int kk = 0; kk < 16; kk++) {
            float a[4], b[4];
            #pragma unroll
            for (int i = 0; i < 4; i++) a[i] = As[kk][ty*4 + i];
            #pragma unroll
            for (int j = 0; j < 4; j++) b[j] = Bs[kk][tx*4 + j];
            #pragma unroll
            for (int i = 0; i < 4; i++)
                #pragma unroll
                for (int j = 0; j < 4; j++) acc[i][j] = fmaf(a[i], b[j], acc[i][j]);
        }
        __syncthreads();
    }
    #pragma unroll
    for (int i = 0; i < 4; i++) {
        int r = ty*4 + i;
        float wv = roww[r];
        size_t base = (size_t)(slot0 + r)*HDIM + hbase + tx*4;
        float4 o;
        float v0 = fmaxf(acc[i][0], 0.0f);
        float v1 = fmaxf(acc[i][1], 0.0f);
        float v2 = fmaxf(acc[i][2], 0.0f);
        float v3 = fmaxf(acc[i][3], 0.0f);
        o.x = v0*v0*wv; o.y = v1*v1*wv; o.z = v2*v2*wv; o.w = v3*v3*wv;
        *(float4*)(g_h + base) = o;
    }
}

// ---------------- PROJ GEMM: outslot[slot, D] = h[slot] @ Wproj[e]^T ----------------
__global__ void proj_kernel(const float* __restrict__ Wproj) {
    const int slot0 = blockIdx.x * 64;
    const int dbase = blockIdx.y * 64;
    __shared__ float As[16][65];
    __shared__ float Bs[16][65];
    int tid = threadIdx.x;
    int e = g_sexp[slot0];
    const float* Ap = g_h + (size_t)slot0 * HDIM;
    const float* Bp = Wproj + ((size_t)e*DDIM + dbase) * HDIM;
    int tx = tid & 15, ty = tid >> 4;
    int lr = tid >> 2;
    int lk = (tid & 3) * 4;
    float acc[4][4];
    #pragma unroll
    for (int i = 0; i < 4; i++)
        #pragma unroll
        for (int j = 0; j < 4; j++) acc[i][j] = 0.0f;

    for (int k0 = 0; k0 < HDIM; k0 += 16) {
        float4 av = *(const float4*)(Ap + (size_t)lr*HDIM + k0 + lk);
        float4 bv = *(const float4*)(Bp + (size_t)lr*HDIM + k0 + lk);
        As[lk+0][lr] = av.x; As[lk+1][lr] = av.y; As[lk+2][lr] = av.z; As[lk+3][lr] = av.w;
        Bs[lk+0][lr] = bv.x; Bs[lk+1][lr] = bv.y; Bs[lk+2][lr] = bv.z; Bs[lk+3][lr] = bv.w;
        __syncthreads();
        #pragma unroll
        for (int kk = 0; kk < 16; kk++) {
            float a[4], b[4];
            #pragma unroll
            for (int i = 0; i < 4; i++) a[i] = As[kk][ty*4 + i];
            #pragma unroll
            for (int j = 0; j < 4; j++) b[j] = Bs[kk][tx*4 + j];
            #pragma unroll
            for (int i = 0; i < 4; i++)
                #pragma unroll
                for (int j = 0; j < 4; j++) acc[i][j] = fmaf(a[i], b[j], acc[i][j]);
        }
        __syncthreads();
    }
    #pragma unroll
    for (int i = 0; i < 4; i++) {
        int r = ty*4 + i;
        size_t base = (size_t)(slot0 + r)*DDIM + dbase + tx*4;
        float4 o;
        o.x = acc[i][0]; o.y = acc[i][1]; o.z = acc[i][2]; o.w = acc[i][3];
        *(float4*)(g_outslot + base) = o;
    }
}

// ---------------- combine: out[n] = outslot[s0] + outslot[s1] ----------------
__global__ void combine_kernel(float* __restrict__ out) {
    int n = blockIdx.x;
    int tid = threadIdx.x;
    int s0 = g_tokslot[n*2], s1 = g_tokslot[n*2+1];
    const float4* a = (const float4*)(g_outslot + (size_t)s0 * DDIM);
    const float4* b = (const float4*)(g_outslot + (size_t)s1 * DDIM);
    float4* o = (float4*)(out + (size_t)n * DDIM);
    for (int d = tid; d < DDIM/4; d += 256) {
        float4 av = a[d], bv = b[d];
        float4 ov;
        ov.x = av.x + bv.x; ov.y = av.y + bv.y;
        ov.z = av.z + bv.z; ov.w = av.w + bv.w;
        o[d] = ov;
    }
}

// ---------------- balance loss (deterministic reduction) ----------------
__global__ void loss_kernel(float* __restrict__ out, int write_loss) {
    __shared__ float red[256];
    __shared__ float acc_sh;
    int tid = threadIdx.x;
    if (tid == 0) acc_sh = 0.0f;
    __syncthreads();
    for (int e = 0; e < NEXP; e++) {
        float s = 0.0f;
        for (int n = tid; n < NTOK; n += 256) s += g_probs[n*NEXP + e];
        red[tid] = s;
        __syncthreads();
        for (int o = 128; o; o >>= 1) {
            if (tid < o) red[tid] += red[tid + o];
            __syncthreads();
        }
        if (tid == 0) {
            float meanp = red[0] / (float)NTOK;
            float freq = (float)g_counts[e] / (float)NTOK;
            acc_sh += meanp * freq;
        }
        __syncthreads();
    }
    if (tid == 0 && write_loss)
        out[(size_t)NTOK * DDIM] = acc_sh * (float)NEXP;
}

// ---------------- launch ----------------
extern "C" void kernel_launch(void* const* d_in, const int* in_sizes, int n_in,
                              void* d_out, int out_size) {
    const float* x   = (const float*)d_in[0];
    const float* Wg  = (const float*)d_in[1];
    const float* Wfc = (const float*)d_in[2];
    const float* Wp  = (const float*)d_in[3];
    float* out = (float*)d_out;

    init_kernel<<<(MAXSLOTS + 255)/256, 256>>>();
    gate_kernel<<<NTOK, 256>>>(x, Wg);
    offsets_kernel<<<1, 32>>>();
    scatter_kernel<<<(NSLOTS + 255)/256, 256>>>();
    dim3 gfc(MTILES, HDIM/64);
    fc_kernel<<<gfc, 256>>>(x, Wfc);
    dim3 gpj(MTILES, DDIM/64);
    proj_kernel<<<gpj, 256>>>(Wp);
    combine_kernel<<<NTOK, 256>>>(out);
    int write_loss = (out_size > NTOK*DDIM) ? 1 : 0;
    loss_kernel<<<1, 256>>>(out, write_loss);
}

// round 4
// speedup vs baseline: 3.7210x; 3.7210x over previous
#include <cuda_runtime.h>
#include <cuda_bf16.h>
#include <cstdint>

// ---------------- problem constants ----------------
#define NTOK   4096
#define DDIM   1024
#define HDIM   4096
#define NEXP   8
#define NSLOTS (NTOK*2)
#define MAXSLOTS 9216            // 8192 + 8*128 pad headroom
#define MTILES (MAXSLOTS/128)    // 72

// ---------------- device scratch ----------------
__device__ float g_probs[NTOK*NEXP];
__device__ int   g_eidx[NSLOTS];
__device__ float g_rw[NSLOTS];
__device__ int   g_counts[NEXP];
__device__ int   g_fill[NEXP];
__device__ int   g_offpad[NEXP+1];
__device__ int   g_list[MAXSLOTS];
__device__ float g_ws[MAXSLOTS];
__device__ int   g_sexp[MAXSLOTS];
__device__ int   g_tokslot[NSLOTS];
__device__ __nv_bfloat16 g_xhi[(size_t)NTOK*DDIM];
__device__ __nv_bfloat16 g_xlo[(size_t)NTOK*DDIM];
__device__ __nv_bfloat16 g_wfchi[(size_t)NEXP*HDIM*DDIM];
__device__ __nv_bfloat16 g_wfclo[(size_t)NEXP*HDIM*DDIM];
__device__ __nv_bfloat16 g_wphi[(size_t)NEXP*DDIM*HDIM];
__device__ __nv_bfloat16 g_wplo[(size_t)NEXP*DDIM*HDIM];
__device__ __nv_bfloat16 g_hhi[(size_t)MAXSLOTS*HDIM];
__device__ __nv_bfloat16 g_hlo[(size_t)MAXSLOTS*HDIM];
__device__ float g_outslot[(size_t)MAXSLOTS*DDIM];

// ---------------- PTX helpers (sm_80-era ops, legal at compute_103) --------
__device__ __forceinline__ uint32_t smem_u32(const void* p) {
    uint32_t a;
    asm("{ .reg .u64 t; cvta.to.shared.u64 t, %1; cvt.u32.u64 %0, t; }" : "=r"(a) : "l"(p));
    return a;
}
__device__ __forceinline__ void cp_async16(uint32_t dst, const void* src) {
    asm volatile("cp.async.ca.shared.global [%0], [%1], 16;" :: "r"(dst), "l"(src));
}
#define CP_COMMIT() asm volatile("cp.async.commit_group;" ::: "memory")
#define CP_WAIT0()  asm volatile("cp.async.wait_group 0;" ::: "memory")
#define CP_WAIT1()  asm volatile("cp.async.wait_group 1;" ::: "memory")

__device__ __forceinline__ void ldsm_x4(uint32_t* r, uint32_t addr) {
    asm volatile("ldmatrix.sync.aligned.m8n8.x4.shared.b16 {%0,%1,%2,%3}, [%4];"
                 : "=r"(r[0]), "=r"(r[1]), "=r"(r[2]), "=r"(r[3]) : "r"(addr));
}
__device__ __forceinline__ void ldsm_x2(uint32_t* r, uint32_t addr) {
    asm volatile("ldmatrix.sync.aligned.m8n8.x2.shared.b16 {%0,%1}, [%2];"
                 : "=r"(r[0]), "=r"(r[1]) : "r"(addr));
}
__device__ __forceinline__ void mma16816(float* d, const uint32_t* a, const uint32_t* b) {
    asm volatile("mma.sync.aligned.m16n8k16.row.col.f32.bf16.bf16.f32 "
        "{%0,%1,%2,%3}, {%4,%5,%6,%7}, {%8,%9}, {%0,%1,%2,%3};"
        : "+f"(d[0]), "+f"(d[1]), "+f"(d[2]), "+f"(d[3])
        : "r"(a[0]), "r"(a[1]), "r"(a[2]), "r"(a[3]), "r"(b[0]), "r"(b[1]));
}

// ---------------- smem layout for the MMA kernels ----------------
// rowtok[128] @0, roww[128] @512, tile buffers @1024
// per matrix per stage: 128 rows * 80B = 10240 B; mats: 0=AHI 1=ALO 2=BHI 3=BLO
#define TBUF(mat, stg) (1024 + ((mat)*2 + (stg))*10240)
#define SM_MMA_TOTAL (1024 + 8*10240)   // 82944

// ---------------- fp32 -> bf16 hi/lo split ----------------
__global__ void cvt_kernel(const float* __restrict__ src, __nv_bfloat16* __restrict__ hi,
                           __nv_bfloat16* __restrict__ lo, int n4) {
    int i = blockIdx.x*blockDim.x + threadIdx.x;
    if (i >= n4) return;
    float4 v = ((const float4*)src)[i];
    __nv_bfloat16 h0 = __float2bfloat16(v.x); __nv_bfloat16 l0 = __float2bfloat16(v.x - __bfloat162float(h0));
    __nv_bfloat16 h1 = __float2bfloat16(v.y); __nv_bfloat16 l1 = __float2bfloat16(v.y - __bfloat162float(h1));
    __nv_bfloat16 h2 = __float2bfloat16(v.z); __nv_bfloat16 l2 = __float2bfloat16(v.z - __bfloat162float(h2));
    __nv_bfloat16 h3 = __float2bfloat16(v.w); __nv_bfloat16 l3 = __float2bfloat16(v.w - __bfloat162float(h3));
    __nv_bfloat162 a, b;
    a.x = h0; a.y = h1; b.x = h2; b.y = h3;
    ((__nv_bfloat162*)hi)[i*2] = a; ((__nv_bfloat162*)hi)[i*2+1] = b;
    a.x = l0; a.y = l1; b.x = l2; b.y = l3;
    ((__nv_bfloat162*)lo)[i*2] = a; ((__nv_bfloat162*)lo)[i*2+1] = b;
}

// ---------------- init ----------------
__global__ void init_kernel() {
    int i = blockIdx.x*blockDim.x + threadIdx.x;
    if (i < NEXP) { g_counts[i] = 0; g_fill[i] = 0; }
    if (i < MAXSLOTS) { g_list[i] = 0; g_ws[i] = 0.0f; g_sexp[i] = 0; }
}

// ---------------- gating ----------------
__global__ void gate_kernel(const float* __restrict__ x, const float* __restrict__ Wg) {
    int n = blockIdx.x;
    int tid = threadIdx.x;
    int w = tid >> 5, lane = tid & 31;
    const float4* xr = (const float4*)(x + (size_t)n * DDIM);
    const float4* gr = (const float4*)(Wg + (size_t)w * DDIM);
    float s = 0.0f;
    #pragma unroll 4
    for (int i = lane; i < DDIM/4; i += 32) {
        float4 a = xr[i], b = gr[i];
        s += a.x*b.x + a.y*b.y + a.z*b.z + a.w*b.w;
    }
    #pragma unroll
    for (int o = 16; o; o >>= 1) s += __shfl_xor_sync(0xFFFFFFFFu, s, o);
    __shared__ float logits[NEXP];
    if (lane == 0) logits[w] = s;
    __syncthreads();
    if (tid == 0) {
        float m = logits[0];
        #pragma unroll
        for (int e = 1; e < NEXP; e++) m = fmaxf(m, logits[e]);
        float p[NEXP]; float sum = 0.0f;
        #pragma unroll
        for (int e = 0; e < NEXP; e++) { p[e] = expf(logits[e] - m); sum += p[e]; }
        float inv = 1.0f / sum;
        #pragma unroll
        for (int e = 0; e < NEXP; e++) { p[e] *= inv; g_probs[n*NEXP + e] = p[e]; }
        int i1 = 0;
        #pragma unroll
        for (int e = 1; e < NEXP; e++) if (p[e] > p[i1]) i1 = e;
        int i2 = -1;
        #pragma unroll
        for (int e = 0; e < NEXP; e++) {
            if (e == i1) continue;
            if (i2 < 0 || p[e] > p[i2]) i2 = e;
        }
        float r = 1.0f / (p[i1] + p[i2]);
        g_eidx[n*2]   = i1;  g_eidx[n*2+1] = i2;
        g_rw[n*2]     = p[i1]*r;  g_rw[n*2+1] = p[i2]*r;
        atomicAdd(&g_counts[i1], 1);
        atomicAdd(&g_counts[i2], 1);
    }
}

// ---------------- 128-aligned per-expert segments ----------------
__global__ void offsets_kernel() {
    if (threadIdx.x == 0) {
        int off = 0;
        for (int e = 0; e < NEXP; e++) {
            g_offpad[e] = off;
            off += ((g_counts[e] + 127) >> 7) << 7;
        }
        g_offpad[NEXP] = off;
    }
}

__global__ void scatter_kernel() {
    int i = blockIdx.x*blockDim.x + threadIdx.x;
    if (i >= NSLOTS) return;
    int e = g_eidx[i];
    int pos = atomicAdd(&g_fill[e], 1);
    int slot = g_offpad[e] + pos;
    g_list[slot] = i >> 1;
    g_ws[slot] = g_rw[i];
    g_sexp[slot] = e;
    g_tokslot[i] = slot;
}

// ---------------- bf16-split HMMA GEMM (fc / proj fused variants) ----------
// CTA tile 128x128, BK=32, 256 thr, 8 warps 2x4, warp tile 64x32 (16 m16n8k16)
template<bool IS_FC>
__global__ void __launch_bounds__(256) mma_kernel() {
    extern __shared__ char smem[];
    const uint32_t sbase = smem_u32(smem);
    const int tid = threadIdx.x;
    const int lane = tid & 31;
    const int wrp = tid >> 5;
    const int wm = wrp >> 2;          // 0..1  -> m offset wm*64
    const int wn = wrp & 3;           // 0..3  -> n offset wn*32
    const int slot0 = blockIdx.x * 128;
    const int nb   = blockIdx.y * 128;  // hbase (fc) or dbase (proj)
    const int KDIM = IS_FC ? DDIM : HDIM;
    const int NITER = KDIM / 32;

    if (slot0 >= g_offpad[NEXP]) return;   // unused pad tile

    int* rowtok_s = (int*)smem;
    float* roww_s = (float*)(smem + 512);
    if (tid < 128) {
        rowtok_s[tid] = g_list[slot0 + tid];
        roww_s[tid]   = g_ws[slot0 + tid];
    }
    __syncthreads();

    const int e = g_sexp[slot0];
    const __nv_bfloat16 *Ah, *Al, *Bh, *Bl;
    if (IS_FC) {
        Ah = g_xhi;  Al = g_xlo;
        Bh = g_wfchi + ((size_t)e*HDIM + nb) * DDIM;
        Bl = g_wfclo + ((size_t)e*HDIM + nb) * DDIM;
    } else {
        Ah = g_hhi + (size_t)slot0 * HDIM;
        Al = g_hlo + (size_t)slot0 * HDIM;
        Bh = g_wphi + ((size_t)e*DDIM + nb) * HDIM;
        Bl = g_wplo + ((size_t)e*DDIM + nb) * HDIM;
    }

    // ---- async tile loader: 512 16B-chunks per matrix, 2 per thread ----
    auto issue_load = [&](int stg, int k0) {
        #pragma unroll
        for (int i = 0; i < 2; i++) {
            int c = tid + i*256;
            int row = c >> 2, seg = c & 3;
            uint32_t soff = (uint32_t)(row*80 + seg*16);
            size_t acol = (size_t)k0 + seg*8;
            size_t arow;
            if (IS_FC) arow = (size_t)rowtok_s[row] * DDIM;
            else       arow = (size_t)row * HDIM;
            cp_async16(sbase + TBUF(0,stg) + soff, Ah + arow + acol);
            cp_async16(sbase + TBUF(1,stg) + soff, Al + arow + acol);
            size_t brow = (size_t)row * KDIM;
            cp_async16(sbase + TBUF(2,stg) + soff, Bh + brow + acol);
            cp_async16(sbase + TBUF(3,stg) + soff, Bl + brow + acol);
        }
    };

    float acc[4][4][4];
    #pragma unroll
    for (int mt = 0; mt < 4; mt++)
        #pragma unroll
        for (int nt = 0; nt < 4; nt++)
            #pragma unroll
            for (int j = 0; j < 4; j++) acc[mt][nt][j] = 0.0f;

    issue_load(0, 0);
    CP_COMMIT();

    // ldmatrix lane address components (byte offsets within a tile buffer)
    const uint32_t a_row = (uint32_t)(lane & 15);
    const uint32_t a_cb  = (uint32_t)((lane >> 4) * 16);
    const uint32_t b_row = (uint32_t)(lane & 7);
    const uint32_t b_cb  = (uint32_t)(((lane >> 3) & 1) * 16);

    for (int it = 0; it < NITER; it++) {
        if (it + 1 < NITER) {
            issue_load((it + 1) & 1, (it + 1) * 32);
            CP_COMMIT();
            CP_WAIT1();
        } else {
            CP_WAIT0();
        }
        __syncthreads();
        const int stg = it & 1;
        const uint32_t bAh = sbase + TBUF(0,stg);
        const uint32_t bAl = sbase + TBUF(1,stg);
        const uint32_t bBh = sbase + TBUF(2,stg);
        const uint32_t bBl = sbase + TBUF(3,stg);
        #pragma unroll
        for (int ks = 0; ks < 2; ks++) {
            uint32_t ahi[4][4], alo[4][4], bhi[4][2], blo[4][2];
            const uint32_t kb = (uint32_t)(ks * 32);
            #pragma unroll
            for (int mt = 0; mt < 4; mt++) {
                uint32_t ro = (uint32_t)(wm*64 + mt*16) + a_row;
                uint32_t off = ro*80 + kb + a_cb;
                ldsm_x4(ahi[mt], bAh + off);
                ldsm_x4(alo[mt], bAl + off);
            }
            #pragma unroll
            for (int nt = 0; nt < 4; nt++) {
                uint32_t ro = (uint32_t)(wn*32 + nt*8) + b_row;
                uint32_t off = ro*80 + kb + b_cb;
                ldsm_x2(bhi[nt], bBh + off);
                ldsm_x2(blo[nt], bBl + off);
            }
            #pragma unroll
            for (int mt = 0; mt < 4; mt++)
                #pragma unroll
                for (int nt = 0; nt < 4; nt++) {
                    mma16816(acc[mt][nt], ahi[mt], bhi[nt]);
                    mma16816(acc[mt][nt], ahi[mt], blo[nt]);
                    mma16816(acc[mt][nt], alo[mt], bhi[nt]);
                }
        }
        __syncthreads();
    }

    // ---- epilogue ----
    #pragma unroll
    for (int mt = 0; mt < 4; mt++) {
        #pragma unroll
        for (int nt = 0; nt < 4; nt++) {
            int r0 = wm*64 + mt*16 + (lane >> 2);
            int c0 = wn*32 + nt*8 + (lane & 3)*2;
            #pragma unroll
            for (int half = 0; half < 2; half++) {
                int r = r0 + half*8;
                float d0 = acc[mt][nt][half*2];
                float d1 = acc[mt][nt][half*2 + 1];
                if (IS_FC) {
                    float wv = roww_s[r];
                    float v0 = fmaxf(d0, 0.0f); v0 = v0*v0*wv;
                    float v1 = fmaxf(d1, 0.0f); v1 = v1*v1*wv;
                    __nv_bfloat16 h0 = __float2bfloat16(v0);
                    __nv_bfloat16 l0 = __float2bfloat16(v0 - __bfloat162float(h0));
                    __nv_bfloat16 h1 = __float2bfloat16(v1);
                    __nv_bfloat16 l1 = __float2bfloat16(v1 - __bfloat162float(h1));
                    __nv_bfloat162 hh; hh.x = h0; hh.y = h1;
                    __nv_bfloat162 ll; ll.x = l0; ll.y = l1;
                    size_t base = (size_t)(slot0 + r)*HDIM + nb + c0;
                    *(__nv_bfloat162*)(g_hhi + base) = hh;
                    *(__nv_bfloat162*)(g_hlo + base) = ll;
                } else {
                    size_t base = (size_t)(slot0 + r)*DDIM + nb + c0;
                    float2 o; o.x = d0; o.y = d1;
                    *(float2*)(g_outslot + base) = o;
                }
            }
        }
    }
}

// ---------------- combine ----------------
__global__ void combine_kernel(float* __restrict__ out) {
    int n = blockIdx.x;
    int tid = threadIdx.x;
    int s0 = g_tokslot[n*2], s1 = g_tokslot[n*2+1];
    const float4* a = (const float4*)(g_outslot + (size_t)s0 * DDIM);
    const float4* b = (const float4*)(g_outslot + (size_t)s1 * DDIM);
    float4* o = (float4*)(out + (size_t)n * DDIM);
    for (int d = tid; d < DDIM/4; d += 256) {
        float4 av = a[d], bv = b[d];
        float4 ov;
        ov.x = av.x + bv.x; ov.y = av.y + bv.y;
        ov.z = av.z + bv.z; ov.w = av.w + bv.w;
        o[d] = ov;
    }
}

// ---------------- balance loss ----------------
__global__ void loss_kernel(float* __restrict__ out, int write_loss) {
    __shared__ float red[256];
    __shared__ float acc_sh;
    int tid = threadIdx.x;
    if (tid == 0) acc_sh = 0.0f;
    __syncthreads();
    for (int e = 0; e < NEXP; e++) {
        float s = 0.0f;
        for (int n = tid; n < NTOK; n += 256) s += g_probs[n*NEXP + e];
        red[tid] = s;
        __syncthreads();
        for (int o = 128; o; o >>= 1) {
            if (tid < o) red[tid] += red[tid + o];
            __syncthreads();
        }
        if (tid == 0) {
            float meanp = red[0] / (float)NTOK;
            float freq = (float)g_counts[e] / (float)NTOK;
            acc_sh += meanp * freq;
        }
        __syncthreads();
    }
    if (tid == 0 && write_loss)
        out[(size_t)NTOK * DDIM] = acc_sh * (float)NEXP;
}

// ---------------- launch ----------------
extern "C" void kernel_launch(void* const* d_in, const int* in_sizes, int n_in,
                              void* d_out, int out_size) {
    const float* x   = (const float*)d_in[0];
    const float* Wg  = (const float*)d_in[1];
    const float* Wfc = (const float*)d_in[2];
    const float* Wp  = (const float*)d_in[3];
    float* out = (float*)d_out;

    cudaFuncSetAttribute(mma_kernel<true>,  cudaFuncAttributeMaxDynamicSharedMemorySize, SM_MMA_TOTAL);
    cudaFuncSetAttribute(mma_kernel<false>, cudaFuncAttributeMaxDynamicSharedMemorySize, SM_MMA_TOTAL);

    __nv_bfloat16 *xhi, *xlo, *wfchi, *wfclo, *wphi, *wplo;
    cudaGetSymbolAddress((void**)&xhi,   g_xhi);
    cudaGetSymbolAddress((void**)&xlo,   g_xlo);
    cudaGetSymbolAddress((void**)&wfchi, g_wfchi);
    cudaGetSymbolAddress((void**)&wfclo, g_wfclo);
    cudaGetSymbolAddress((void**)&wphi,  g_wphi);
    cudaGetSymbolAddress((void**)&wplo,  g_wplo);

    int n4x = NTOK*DDIM/4;
    int n4w = NEXP*HDIM*DDIM/4;
    cvt_kernel<<<(n4x + 255)/256, 256>>>(x,   xhi,   xlo,   n4x);
    cvt_kernel<<<(n4w + 255)/256, 256>>>(Wfc, wfchi, wfclo, n4w);
    cvt_kernel<<<(n4w + 255)/256, 256>>>(Wp,  wphi,  wplo,  n4w);

    init_kernel<<<(MAXSLOTS + 255)/256, 256>>>();
    gate_kernel<<<NTOK, 256>>>(x, Wg);
    offsets_kernel<<<1, 32>>>();
    scatter_kernel<<<(NSLOTS + 255)/256, 256>>>();

    dim3 gfc(MTILES, HDIM/128);
    mma_kernel<true><<<gfc, 256, SM_MMA_TOTAL>>>();
    dim3 gpj(MTILES, DDIM/128);
    mma_kernel<false><<<gpj, 256, SM_MMA_TOTAL>>>();

    combine_kernel<<<NTOK, 256>>>(out);
    int write_loss = (out_size > NTOK*DDIM) ? 1 : 0;
    loss_kernel<<<1, 256>>>(out, write_loss);
}